// round 7
// baseline (speedup 1.0000x reference)
#include <cuda_runtime.h>
#include <cstdint>

#define NPTS   100000
#define PPROP  256
#define RFEAT  256
#define CO     21
#define NCHUNK 74
#define CHUNK  1352      // 74*1352 = 100048 >= 100000
#define CPAD   1536      // padded chunk (48 u32 mask words)
#define NWORD  48
#define TILE   32        // points per feature tile (= one mask word)
#define PG     64        // proposals per block

// Scratch (__device__ globals: allocation-free rule)
__device__ float g_partial[NCHUNK][PPROP][RFEAT];   // 19.4 MB
__device__ float g_pcounts[NCHUNK][PPROP];
__device__ float g_cls[PPROP * CO];
__device__ float g_obj[PPROP * CO];

__device__ __forceinline__ void cp16(uint32_t saddr, const void* gptr) {
    asm volatile("cp.async.cg.shared.global [%0], [%1], 16;\n"
                 :: "r"(saddr), "l"(gptr));
}
__device__ __forceinline__ void cp_commit() {
    asm volatile("cp.async.commit_group;\n");
}
__device__ __forceinline__ void cp_wait1() {
    asm volatile("cp.async.wait_group 1;\n");
}
#define ADD_F32X2(out, a, b) \
    asm("add.rn.f32x2 %0, %1, %2;" : "=l"(out) : "l"(a), "l"(b))

struct PoolSmem {
    union {
        float4 sf[3][TILE][64];   // 96 KB feature triple-buffer
        float4 sxyz4[CPAD];       // 24 KB padded xyz (phase A only)
    } u;
    unsigned smask[PG][NWORD];    // 12 KB bitmaps
    float    scnt[8][PG];         // 2 KB
};
#define POOL_SMEM_BYTES ((int)sizeof(PoolSmem))

// ---------------------------------------------------------------------------
// Kernel 1: sparse ROI pooling.
// grid = (74 chunks, 4 proposal-groups), block = 512, 2 CTAs/SM.
// Phase A: stage chunk xyz as float4 -> full-chunk 1536-bit mask per proposal
//          (thread t: proposal t&63, points [192q, 192q+192), q = t>>6;
//          one broadcast LDS.128 per point test).
// Phase B: TRIPLE-buffered cp.async tiles (32 pts x 256 f32), ONE
//          __syncthreads per tile: issuing tile t+2 into buf (t+2)%3 reuses
//          tile t-1's buffer, already consumed by all warps before the
//          iteration-t barrier. Warp w owns proposals [4w,4w+4) and ALL 256
//          features; per membership: 2x LDS.128 + 4x packed f32x2 adds.
// ---------------------------------------------------------------------------
__global__ __launch_bounds__(512, 2)
void pool_kernel(const float* __restrict__ proposals,
                 const float* __restrict__ xyz,
                 const float* __restrict__ feats)
{
    extern __shared__ char smem_raw[];
    PoolSmem* s = reinterpret_cast<PoolSmem*>(smem_raw);

    const int chunk = blockIdx.x;
    const int pbase = blockIdx.y * PG;
    const int tid   = threadIdx.x;
    const int w     = tid >> 5;
    const int l     = tid & 31;
    const int pm    = tid & 63;   // proposal this thread masks
    const int q     = tid >> 6;   // point range [192q, 192q+192)

    const int base = chunk * CHUNK;
    const int nPts = (NPTS - base < CHUNK) ? (NPTS - base) : CHUNK;

    // ---- Phase A: stage xyz as padded float4 (pad 2.0 -> outside all boxes)
    {
        const float* gx = xyz + (size_t)base * 3;
#pragma unroll
        for (int k = 0; k < 3; k++) {               // 3*512 = 1536 = CPAD
            const int j = tid + k * 512;
            float x = 2.f, y = 2.f, z = 2.f;
            if (j < nPts) { x = gx[3*j]; y = gx[3*j+1]; z = gx[3*j+2]; }
            s->u.sxyz4[j] = make_float4(x, y, z, 0.f);
        }
    }

    // Box bounds, bit-exact vs reference (no FMA contraction).
    float alox, ahix, aloy, ahiy, aloz, ahiz;
    {
        const float* pr = proposals + (size_t)(pbase + pm) * 6;
        const float cx = pr[0], cy = pr[1], cz = pr[2];
        const float hx = __fmul_rn(pr[3], 0.5f);
        const float hy = __fmul_rn(pr[4], 0.5f);
        const float hz = __fmul_rn(pr[5], 0.5f);
        alox = __fsub_rn(cx, hx);  ahix = __fadd_rn(cx, hx);
        aloy = __fsub_rn(cy, hy);  ahiy = __fadd_rn(cy, hy);
        aloz = __fsub_rn(cz, hz);  ahiz = __fadd_rn(cz, hz);
    }
    __syncthreads();

    // ---- Build masks: 6 words of 32 tests each (one LDS.128 per test) ----
    {
        float cnt = 0.f;
#pragma unroll
        for (int wd = 0; wd < 6; wd++) {
            unsigned bits = 0;
#pragma unroll
            for (int k = 0; k < 32; k++) {
                const float4 v = s->u.sxyz4[q * 192 + wd * 32 + k];
                const bool in = (v.x >= alox) & (v.x <= ahix) &
                                (v.y >= aloy) & (v.y <= ahiy) &
                                (v.z >= aloz) & (v.z <= ahiz);
                bits |= ((unsigned)in) << k;
            }
            s->smask[pm][q * 6 + wd] = bits;
            cnt += (float)__popc(bits);
        }
        s->scnt[q][pm] = cnt;
    }
    __syncthreads();   // masks done; xyz area now reusable for features

    if (tid < PG) {
        float c = 0.f;
#pragma unroll
        for (int k = 0; k < 8; k++) c += s->scnt[k][tid];
        g_pcounts[chunk][pbase + tid] = c;
    }

    // ---- Phase B: triple-buffered pipelined accumulation ----
    ulonglong2 accA[4], accB[4];
#pragma unroll
    for (int j = 0; j < 4; j++) {
        accA[j].x = 0ull; accA[j].y = 0ull;
        accB[j].x = 0ull; accB[j].y = 0ull;
    }

    const float4* gf = reinterpret_cast<const float4*>(feats);
    const int ntiles = (nPts + TILE - 1) / TILE;

    const int ci = tid >> 6;   // base point within tile (0..7)
    const int cf = tid & 63;   // float4 column

    auto issue = [&](int t, int buf) {
        const int t0 = t * TILE;
#pragma unroll
        for (int k = 0; k < 4; k++) {
            const int i = ci + 8 * k;
            const int pt = t0 + i;
            if (pt < nPts) {
                uint32_t sa = (uint32_t)__cvta_generic_to_shared(&s->u.sf[buf][i][cf]);
                cp16(sa, gf + (size_t)(base + pt) * 64 + cf);
            }
        }
        cp_commit();
    };

    issue(0, 0);
    issue(1, 1);
    int bcur = 0, bnext = 2;   // bcur = t%3, bnext = (t+2)%3
    for (int t = 0; t < ntiles; t++) {
        cp_wait1();          // this thread's group t landed (t+1 in flight)
        __syncthreads();     // tile t visible to all; tile t-1 consumed by all

        if (t + 2 < ntiles) issue(t + 2, bnext);
        else cp_commit();    // keep group count aligned

#pragma unroll
        for (int j = 0; j < 4; j++) {
            unsigned m = s->smask[(w << 2) + j][t];
            while (m) {
                const int i = __ffs(m) - 1;
                m &= m - 1;
                const ulonglong2 va =
                    *reinterpret_cast<const ulonglong2*>(&s->u.sf[bcur][i][l]);
                const ulonglong2 vb =
                    *reinterpret_cast<const ulonglong2*>(&s->u.sf[bcur][i][l + 32]);
                ADD_F32X2(accA[j].x, accA[j].x, va.x);
                ADD_F32X2(accA[j].y, accA[j].y, va.y);
                ADD_F32X2(accB[j].x, accB[j].x, vb.x);
                ADD_F32X2(accB[j].y, accB[j].y, vb.y);
            }
        }
        bcur  = (bcur  == 2) ? 0 : bcur  + 1;
        bnext = (bnext == 2) ? 0 : bnext + 1;
    }

    // Write partial sums (coalesced 512B bursts)
#pragma unroll
    for (int j = 0; j < 4; j++) {
        const int p = (w << 2) + j;
        ulonglong2* row =
            reinterpret_cast<ulonglong2*>(&g_partial[chunk][pbase + p][0]);
        row[l]      = accA[j];
        row[l + 32] = accB[j];
    }
}

// ---------------------------------------------------------------------------
// Kernel 2: reduce partials -> roi -> logits (warp-parallel dots).
// grid = 256 (block per proposal), block = 256. Deep-MLP chunk sum.
// ---------------------------------------------------------------------------
__global__ __launch_bounds__(256)
void reduce_kernel(const float* __restrict__ W_cls, const float* __restrict__ b_cls,
                   const float* __restrict__ W_obj, const float* __restrict__ b_obj)
{
    const int p   = blockIdx.x;
    const int tid = threadIdx.x;
    const int w   = tid >> 5;
    const int l   = tid & 31;

    __shared__ float roi[RFEAT];
    __shared__ float sc[8];

    float s0 = 0.f, s1 = 0.f, s2 = 0.f, s3 = 0.f;
#pragma unroll
    for (int c = 0; c < 72; c += 4) {
        s0 += g_partial[c    ][p][tid];
        s1 += g_partial[c + 1][p][tid];
        s2 += g_partial[c + 2][p][tid];
        s3 += g_partial[c + 3][p][tid];
    }
    s0 += g_partial[72][p][tid];
    s1 += g_partial[73][p][tid];
    const float sum = (s0 + s1) + (s2 + s3);

    float cv = (tid < NCHUNK) ? g_pcounts[tid][p] : 0.f;
#pragma unroll
    for (int o = 16; o > 0; o >>= 1) cv += __shfl_down_sync(0xffffffffu, cv, o);
    if (l == 0) sc[w] = cv;
    __syncthreads();
    if (tid == 0) {
        float t = 0.f;
#pragma unroll
        for (int i = 0; i < 8; i++) t += sc[i];
        sc[0] = 1.0f / fmaxf(t, 1.0f);
    }
    __syncthreads();
    roi[tid] = sum * sc[0];
    __syncthreads();

    for (int o = w; o < 2 * CO; o += 8) {
        const bool isobj = o >= CO;
        const int  j     = isobj ? o - CO : o;
        const float* Wm  = isobj ? W_obj : W_cls;
        float a = 0.f;
#pragma unroll
        for (int f = l; f < RFEAT; f += 32) a += roi[f] * Wm[f * CO + j];
#pragma unroll
        for (int off = 16; off > 0; off >>= 1)
            a += __shfl_xor_sync(0xffffffffu, a, off);
        if (l == 0)
            (isobj ? g_obj : g_cls)[p * CO + j] = a + (isobj ? b_obj[j] : b_cls[j]);
    }
}

// ---------------------------------------------------------------------------
// Kernel 3: softmaxes + product. 1 block, 256 threads.
// ---------------------------------------------------------------------------
__global__ __launch_bounds__(256)
void softmax_kernel(float* __restrict__ out)
{
    const int tid = threadIdx.x;
    __shared__ float sobj[PPROP * CO];   // 21 KB
    __shared__ float red[CO][12];
    __shared__ float cmax[CO], cinv[CO];

    for (int e = tid; e < PPROP * CO; e += 256) sobj[e] = g_obj[e];
    __syncthreads();

    const int c = tid / 12;   // column (0..20) for tid < 252
    const int r = tid % 12;

    if (tid < 252) {
        float m = -3.4e38f;
        for (int p = r; p < PPROP; p += 12) m = fmaxf(m, sobj[p * CO + c]);
        red[c][r] = m;
    }
    __syncthreads();
    if (tid < CO) {
        float m = red[tid][0];
#pragma unroll
        for (int k = 1; k < 12; k++) m = fmaxf(m, red[tid][k]);
        cmax[tid] = m;
    }
    __syncthreads();
    if (tid < 252) {
        const float m = cmax[c];
        float sm = 0.f;
        for (int p = r; p < PPROP; p += 12) {
            const float e = expf(sobj[p * CO + c] - m);
            sobj[p * CO + c] = e;
            sm += e;
        }
        red[c][r] = sm;
    }
    __syncthreads();
    if (tid < CO) {
        float sm = 0.f;
#pragma unroll
        for (int k = 0; k < 12; k++) sm += red[tid][k];
        cinv[tid] = 1.0f / sm;
    }

    float lg[CO];
    {
        float m = -3.4e38f;
#pragma unroll
        for (int j = 0; j < CO; j++) { lg[j] = g_cls[tid * CO + j]; m = fmaxf(m, lg[j]); }
        float sm = 0.f;
#pragma unroll
        for (int j = 0; j < CO; j++) { lg[j] = expf(lg[j] - m); sm += lg[j]; }
        const float invs = 1.0f / sm;
#pragma unroll
        for (int j = 0; j < CO; j++) lg[j] *= invs;
    }
    __syncthreads();

#pragma unroll
    for (int j = 0; j < CO; j++)
        out[tid * CO + j] = lg[j] * sobj[tid * CO + j] * cinv[j];
}

// ---------------------------------------------------------------------------
extern "C" void kernel_launch(void* const* d_in, const int* in_sizes, int n_in,
                              void* d_out, int out_size)
{
    const float* proposals = (const float*)d_in[0];
    const float* input_xyz = (const float*)d_in[1];
    const float* seg_feats = (const float*)d_in[2];
    const float* W_cls     = (const float*)d_in[3];
    const float* b_cls     = (const float*)d_in[4];
    const float* W_obj     = (const float*)d_in[5];
    const float* b_obj     = (const float*)d_in[6];
    float* out = (float*)d_out;

    (void)in_sizes; (void)n_in; (void)out_size;

    cudaFuncSetAttribute(pool_kernel,
                         cudaFuncAttributeMaxDynamicSharedMemorySize,
                         POOL_SMEM_BYTES);
    pool_kernel<<<dim3(NCHUNK, 4), 512, POOL_SMEM_BYTES>>>(proposals, input_xyz, seg_feats);
    reduce_kernel<<<PPROP, 256>>>(W_cls, b_cls, W_obj, b_obj);
    softmax_kernel<<<1, 256>>>(out);
}